// round 1
// baseline (speedup 1.0000x reference)
#include <cuda_runtime.h>
#include <cuda_bf16.h>

#define N_NEURONS 4096
#define N_EDGES   131072
#define VOCAB     8192
#define BB        8
#define TT        128
#define NB        (N_NEURONS*BB)   /* 32768 state elements */
#define DECAYF    0.99f

#define RBLK  128
#define RTHR  256
#define NWARP ((RBLK*RTHR)/32)     /* 1024 warps */
#define NPW   (N_NEURONS/NWARP)    /* 4 neurons per warp */

/* ------------------ static device scratch (no allocation) ------------------ */
__device__ float g_Xall[TT*NB];                  /* (t, n, b)  16MB */
__device__ float g_xs  [TT*NB];                  /* (t, n, b)  16MB */
__device__ float g_xsT [BB*TT*N_NEURONS];        /* (b*T+t, n) 16MB */
__device__ float g_x[NB];
__device__ float g_y[NB];
__device__ float g_A[NB];
__device__ float g_sigma[N_EDGES];
__device__ int   g_srcs [N_EDGES];
__device__ float g_Gss  [N_EDGES];
__device__ float g_Gxs  [N_EDGES];
__device__ float g_Gys  [N_EDGES];
__device__ int   g_perm [N_EDGES];
__device__ int   g_counts[N_NEURONS];
__device__ int   g_cursor[N_NEURONS];
__device__ int   g_rowptr[N_NEURONS+1];

__device__ unsigned          g_cnt = 0;
__device__ volatile unsigned g_gen = 0;

/* ------------------ preprocessing: CSR by dst (deterministic) -------------- */
__global__ void k_zero_counts() {
    int i = blockIdx.x*blockDim.x + threadIdx.x;
    if (i < N_NEURONS) g_counts[i] = 0;
}

__global__ void k_hist(const int* __restrict__ dst) {
    int e = blockIdx.x*blockDim.x + threadIdx.x;
    if (e < N_EDGES) atomicAdd(&g_counts[dst[e]], 1);
}

__global__ void k_scan() {
    __shared__ int sh[1024];
    int tid  = threadIdx.x;
    int base = tid*4;
    int v0 = g_counts[base+0], v1 = g_counts[base+1];
    int v2 = g_counts[base+2], v3 = g_counts[base+3];
    int s = v0+v1+v2+v3;
    sh[tid] = s;
    __syncthreads();
    for (int off = 1; off < 1024; off <<= 1) {
        int t = (tid >= off) ? sh[tid-off] : 0;
        __syncthreads();
        sh[tid] += t;
        __syncthreads();
    }
    int excl = sh[tid] - s;
    g_rowptr[base+0] = excl; g_cursor[base+0] = excl; excl += v0;
    g_rowptr[base+1] = excl; g_cursor[base+1] = excl; excl += v1;
    g_rowptr[base+2] = excl; g_cursor[base+2] = excl; excl += v2;
    g_rowptr[base+3] = excl; g_cursor[base+3] = excl; excl += v3;
    if (tid == 1023) g_rowptr[N_NEURONS] = excl;
}

__global__ void k_scatter(const int* __restrict__ dst) {
    int e = blockIdx.x*blockDim.x + threadIdx.x;
    if (e < N_EDGES) {
        int p = atomicAdd(&g_cursor[dst[e]], 1);
        g_perm[p] = e;
    }
}

/* sort each bin ascending by original edge id -> fully deterministic layout */
__global__ void k_sortbins() {
    int n = blockIdx.x*blockDim.x + threadIdx.x;
    if (n >= N_NEURONS) return;
    int rs = g_rowptr[n], re = g_rowptr[n+1];
    for (int i = rs+1; i < re; i++) {
        int key = g_perm[i];
        int j = i-1;
        while (j >= rs && g_perm[j] > key) { g_perm[j+1] = g_perm[j]; j--; }
        g_perm[j+1] = key;
    }
}

__global__ void k_gather(const int* __restrict__ src, const float* __restrict__ Gs,
                         const float* __restrict__ Gx, const float* __restrict__ Gy) {
    int i = blockIdx.x*blockDim.x + threadIdx.x;
    if (i < N_EDGES) {
        int e = g_perm[i];
        g_srcs[i]  = src[e];
        g_Gss[i]   = Gs[e];
        g_Gxs[i]   = Gx[e];
        g_Gys[i]   = Gy[e];
        g_sigma[i] = 0.0f;
    }
}

/* ------------------ embedding gather: Xall[t][n][b] = Wemb[idx[b][t]][n] --- */
__global__ void k_embed(const int* __restrict__ idx, const float* __restrict__ Wemb) {
    int id = blockIdx.x*blockDim.x + threadIdx.x;   /* id = t*4096 + n */
    if (id >= TT*N_NEURONS) return;
    int t = id >> 12;
    int n = id & (N_NEURONS-1);
    float v[8];
#pragma unroll
    for (int b = 0; b < 8; b++)
        v[b] = Wemb[(size_t)idx[b*TT + t]*N_NEURONS + n];
    float4* o = (float4*)&g_Xall[(size_t)id*8];
    o[0] = make_float4(v[0], v[1], v[2], v[3]);
    o[1] = make_float4(v[4], v[5], v[6], v[7]);
}

/* ------------------ persistent recurrent kernel ---------------------------- */
__device__ __forceinline__ void gbar() {
    __threadfence();
    __syncthreads();
    if (threadIdx.x == 0) {
        unsigned gen = g_gen;
        if (atomicAdd(&g_cnt, 1u) == (unsigned)(RBLK-1)) {
            g_cnt = 0;
            __threadfence();
            g_gen = gen + 1;
        } else {
            while (g_gen == gen) { }
        }
    }
    __syncthreads();
}

__global__ void __launch_bounds__(RTHR) k_recurrent() {
    const int warp = (blockIdx.x*RTHR + threadIdx.x) >> 5;
    const int lane = threadIdx.x & 31;
    const int e4   = lane >> 3;        /* 4 edge lanes */
    const int b    = lane & 7;         /* 8 batch lanes */
    const unsigned gmask = 0xFFu << (e4*8);

    /* y0 = X[:,0,:] */
    for (int i = 0; i < NPW; i++) {
        int n = warp + NWARP*i;
        if (e4 == 0) __stcg(&g_y[n*8 + b], g_Xall[n*8 + b]);
    }
    gbar();

    for (int t = 0; t < TT; t++) {
        const float* xin = g_Xall + (size_t)t*NB;
        for (int layer = 0; layer < 2; layer++) {
            /* ---- pass1: A[n] = sum_e x[src]*sigma ; sigma update (hebbian) */
            for (int i = 0; i < NPW; i++) {
                int n  = warp + NWARP*i;
                int rs = g_rowptr[n], re = g_rowptr[n+1];
                float xn  = __ldcg(&xin[n*8 + b]);
                float acc = 0.0f;
                for (int j = rs + e4; j < re; j += 4) {
                    int   s   = g_srcs[j];
                    float sig = g_sigma[j];            /* warp-private: L1 ok */
                    float xv  = __ldcg(&xin[s*8 + b]);
                    float yv  = __ldcg(&g_y[s*8 + b]);
                    acc = fmaf(xv, sig, acc);
                    float p = yv * xn;
                    p += __shfl_xor_sync(gmask, p, 1);
                    p += __shfl_xor_sync(gmask, p, 2);
                    p += __shfl_xor_sync(gmask, p, 4);
                    if (b == 0) {
                        float heb = p * 0.125f;
                        g_sigma[j] = (sig + heb * g_Gss[j]) * DECAYF;
                    }
                }
                acc += __shfl_xor_sync(0xffffffffu, acc, 8);
                acc += __shfl_xor_sync(0xffffffffu, acc, 16);
                if (e4 == 0) __stcg(&g_A[n*8 + b], acc);
            }
            gbar();
            /* ---- pass2: y[n] = sum_e relu(A[src])*Gy */
            for (int i = 0; i < NPW; i++) {
                int n  = warp + NWARP*i;
                int rs = g_rowptr[n], re = g_rowptr[n+1];
                float acc = 0.0f;
                for (int j = rs + e4; j < re; j += 4) {
                    int   s  = g_srcs[j];
                    float av = __ldcg(&g_A[s*8 + b]);
                    av = av > 0.0f ? av : 0.0f;
                    acc = fmaf(av, g_Gys[j], acc);
                }
                acc += __shfl_xor_sync(0xffffffffu, acc, 8);
                acc += __shfl_xor_sync(0xffffffffu, acc, 16);
                if (e4 == 0) __stcg(&g_y[n*8 + b], acc);
            }
            gbar();
            /* ---- pass3: x[n] = relu(sum_e y[src]*Gx) */
            float* xout = (layer == 0) ? g_x : (g_xs + (size_t)t*NB);
            for (int i = 0; i < NPW; i++) {
                int n  = warp + NWARP*i;
                int rs = g_rowptr[n], re = g_rowptr[n+1];
                float acc = 0.0f;
                for (int j = rs + e4; j < re; j += 4) {
                    int   s  = g_srcs[j];
                    float yv = __ldcg(&g_y[s*8 + b]);
                    acc = fmaf(yv, g_Gxs[j], acc);
                }
                acc += __shfl_xor_sync(0xffffffffu, acc, 8);
                acc += __shfl_xor_sync(0xffffffffu, acc, 16);
                if (e4 == 0) __stcg(&xout[n*8 + b], acc > 0.0f ? acc : 0.0f);
            }
            gbar();
            xin = g_x;
        }
    }
}

/* ------------------ transpose xs (t,n,b) -> xsT (b*T+t, n) ----------------- */
__global__ void k_transpose() {
    int id = blockIdx.x*blockDim.x + threadIdx.x;   /* t*4096 + n */
    if (id >= TT*N_NEURONS) return;
    int t = id >> 12;
    int n = id & (N_NEURONS-1);
    const float4* p = (const float4*)&g_xs[(size_t)id*8];
    float4 v0 = p[0], v1 = p[1];
    float v[8] = {v0.x, v0.y, v0.z, v0.w, v1.x, v1.y, v1.z, v1.w};
#pragma unroll
    for (int bb = 0; bb < 8; bb++)
        g_xsT[((size_t)(bb*TT + t))*N_NEURONS + n] = v[bb];
}

/* ------------------ GEMM: logits[r=(b*T+t)][v] = xsT[r]·W[v] + bias[v] ----- */
__global__ void __launch_bounds__(256) k_gemm(const float* __restrict__ W,
                                              const float* __restrict__ bias,
                                              float* __restrict__ out) {
    __shared__ float As[16][128+4];
    __shared__ float Bs[16][128+4];
    const int tid = threadIdx.x;
    const int tx = tid & 15, ty = tid >> 4;
    const int bv = blockIdx.x;          /* 0..63  : vocab tile   */
    const int br = blockIdx.y;          /* 0..7   : row tile     */
    const float* Ab = g_xsT + (size_t)br*128*N_NEURONS;
    const float* Bb = W     + (size_t)bv*128*N_NEURONS;
    const int lr = tid >> 2;            /* 0..63 */
    const int lc = (tid & 3) << 2;      /* 0,4,8,12 */
    float acc[8][8];
#pragma unroll
    for (int i = 0; i < 8; i++)
#pragma unroll
        for (int j = 0; j < 8; j++) acc[i][j] = 0.0f;

    for (int k0 = 0; k0 < N_NEURONS; k0 += 16) {
        float4 a0 = *(const float4*)(Ab + (size_t)lr*N_NEURONS       + k0 + lc);
        float4 a1 = *(const float4*)(Ab + (size_t)(lr+64)*N_NEURONS  + k0 + lc);
        float4 b0 = *(const float4*)(Bb + (size_t)lr*N_NEURONS       + k0 + lc);
        float4 b1 = *(const float4*)(Bb + (size_t)(lr+64)*N_NEURONS  + k0 + lc);
        __syncthreads();
        As[lc+0][lr]    = a0.x; As[lc+1][lr]    = a0.y; As[lc+2][lr]    = a0.z; As[lc+3][lr]    = a0.w;
        As[lc+0][lr+64] = a1.x; As[lc+1][lr+64] = a1.y; As[lc+2][lr+64] = a1.z; As[lc+3][lr+64] = a1.w;
        Bs[lc+0][lr]    = b0.x; Bs[lc+1][lr]    = b0.y; Bs[lc+2][lr]    = b0.z; Bs[lc+3][lr]    = b0.w;
        Bs[lc+0][lr+64] = b1.x; Bs[lc+1][lr+64] = b1.y; Bs[lc+2][lr+64] = b1.z; Bs[lc+3][lr+64] = b1.w;
        __syncthreads();
#pragma unroll
        for (int k = 0; k < 16; k++) {
            float ar[8], bc[8];
#pragma unroll
            for (int i = 0; i < 8; i++) ar[i] = As[k][ty*8 + i];
#pragma unroll
            for (int j = 0; j < 8; j++) bc[j] = Bs[k][tx*8 + j];
#pragma unroll
            for (int i = 0; i < 8; i++)
#pragma unroll
                for (int j = 0; j < 8; j++)
                    acc[i][j] = fmaf(ar[i], bc[j], acc[i][j]);
        }
    }
    const int r0 = br*128 + ty*8;
    const int v0 = bv*128 + tx*8;
#pragma unroll
    for (int i = 0; i < 8; i++)
#pragma unroll
        for (int j = 0; j < 8; j++)
            out[(size_t)(r0+i)*VOCAB + v0 + j] = acc[i][j] + bias[v0 + j];
}

/* ------------------ sigma_final scatter back to original edge order -------- */
__global__ void k_sigma_out(float* __restrict__ out) {
    int i = blockIdx.x*blockDim.x + threadIdx.x;
    if (i < N_EDGES) out[g_perm[i]] = g_sigma[i];
}

/* ------------------ launch ------------------------------------------------- */
extern "C" void kernel_launch(void* const* d_in, const int* in_sizes, int n_in,
                              void* d_out, int out_size) {
    const int*   idx  = (const int*)  d_in[0];
    const int*   src  = (const int*)  d_in[1];
    const int*   dst  = (const int*)  d_in[2];
    const float* Wemb = (const float*)d_in[3];
    const float* Gx   = (const float*)d_in[4];
    const float* Gy   = (const float*)d_in[5];
    const float* Gs   = (const float*)d_in[6];
    const float* Wout = (const float*)d_in[7];
    const float* bout = (const float*)d_in[8];
    float* out = (float*)d_out;

    k_zero_counts<<<16, 256>>>();
    k_hist<<<512, 256>>>(dst);
    k_scan<<<1, 1024>>>();
    k_scatter<<<512, 256>>>(dst);
    k_sortbins<<<16, 256>>>();
    k_gather<<<512, 256>>>(src, Gs, Gx, Gy);
    k_embed<<<(TT*N_NEURONS)/256, 256>>>(idx, Wemb);
    k_recurrent<<<RBLK, RTHR>>>();
    k_transpose<<<(TT*N_NEURONS)/256, 256>>>();
    dim3 gg(VOCAB/128, (BB*TT)/128);
    k_gemm<<<gg, 256>>>(Wout, bout, out);
    long long btv = (long long)BB*TT*VOCAB;
    if ((long long)out_size >= btv + N_EDGES)
        k_sigma_out<<<512, 256>>>(out + btv);
}

// round 2
// speedup vs baseline: 2.0855x; 2.0855x over previous
#include <cuda_runtime.h>
#include <cuda_bf16.h>

#define N_NEURONS 4096
#define N_EDGES   131072
#define VOCAB     8192
#define BB        8
#define TT        128
#define NB        (N_NEURONS*BB)
#define DECAYF    0.99f

#define RBLK   128
#define RTHR   512
#define NWARPS 16                      /* warps per CTA */
#define NWARP  (RBLK*NWARPS)           /* 2048 warps total */
#define NPW    (N_NEURONS/NWARP)       /* 2 neurons per warp */
#define CAP    1792                    /* per-CTA staged edges (avg ~1024) */
#define MAXB   128                     /* max edges per neuron (actual ~60) */

/* ------------------ static device scratch ------------------ */
__device__ float g_Xall[TT*NB];                  /* (t,n,b) */
__device__ float g_xs  [TT*NB];                  /* (t,n,b) */
__device__ float g_xsT [BB*TT*N_NEURONS];        /* (b*T+t, n) */
__device__ float g_x[NB];
__device__ float g_y[NB];
__device__ float g_A[NB];
__device__ int   g_perm [N_EDGES];
__device__ int   g_counts[N_NEURONS];            /* zero-init; re-zeroed in k_scan */
__device__ int   g_cursor[N_NEURONS];
__device__ int   g_rowptr[N_NEURONS+1];

__device__ unsigned          g_cnt = 0;
__device__ volatile unsigned g_gen = 0;

/* ------------------ CSR preprocessing ------------------ */
__global__ void k_hist(const int* __restrict__ dst) {
    int e = blockIdx.x*blockDim.x + threadIdx.x;
    if (e < N_EDGES) atomicAdd(&g_counts[dst[e]], 1);
}

__global__ void k_scan() {
    __shared__ int sh[1024];
    int tid  = threadIdx.x;
    int base = tid*4;
    int v0 = g_counts[base+0], v1 = g_counts[base+1];
    int v2 = g_counts[base+2], v3 = g_counts[base+3];
    int s = v0+v1+v2+v3;
    sh[tid] = s;
    __syncthreads();
    for (int off = 1; off < 1024; off <<= 1) {
        int t = (tid >= off) ? sh[tid-off] : 0;
        __syncthreads();
        sh[tid] += t;
        __syncthreads();
    }
    int excl = sh[tid] - s;
    g_rowptr[base+0] = excl; g_cursor[base+0] = excl; excl += v0;
    g_rowptr[base+1] = excl; g_cursor[base+1] = excl; excl += v1;
    g_rowptr[base+2] = excl; g_cursor[base+2] = excl; excl += v2;
    g_rowptr[base+3] = excl; g_cursor[base+3] = excl; excl += v3;
    if (tid == 1023) g_rowptr[N_NEURONS] = excl;
    /* restore zeros for the next call (graph replay) */
    g_counts[base+0] = 0; g_counts[base+1] = 0;
    g_counts[base+2] = 0; g_counts[base+3] = 0;
}

__global__ void k_scatter(const int* __restrict__ dst) {
    int e = blockIdx.x*blockDim.x + threadIdx.x;
    if (e < N_EDGES) {
        int p = atomicAdd(&g_cursor[dst[e]], 1);
        g_perm[p] = e;
    }
}

/* ------------------ persistent recurrent kernel ------------------ */
__device__ __forceinline__ void gbar() {
    __threadfence();
    __syncthreads();
    if (threadIdx.x == 0) {
        unsigned gen = g_gen;
        if (atomicAdd(&g_cnt, 1u) == (unsigned)(RBLK-1)) {
            g_cnt = 0;
            __threadfence();
            g_gen = gen + 1;
        } else {
            while (g_gen == gen) { }
        }
    }
    __syncthreads();
}

__device__ __forceinline__ float ldst(const float* base, int o, int b4) {
    return __ldcg((const float*)((const char*)base + (size_t)(o + b4)));
}

__global__ void __launch_bounds__(RTHR) k_recurrent(
        const int* __restrict__ idx, const float* __restrict__ Wemb,
        const int* __restrict__ srcA, const float* __restrict__ GxA,
        const float* __restrict__ GyA, const float* __restrict__ GsA,
        float* __restrict__ sig_out)
{
    __shared__ int   s_soff[CAP];
    __shared__ float s_gs[CAP], s_gx[CAP], s_gy[CAP], s_sig[CAP];
    __shared__ int   s_wcnt[NWARPS], s_wbase[NWARPS+1];

    const int tid  = threadIdx.x;
    const int wid  = tid >> 5;
    const int lane = tid & 31;
    const int warp = blockIdx.x*NWARPS + wid;
    const int e4   = lane >> 3;
    const int b    = lane & 7;
    const int b4   = b*4;
    const unsigned gmask = 0xFFu << (e4*8);
    const int gtid = blockIdx.x*RTHR + tid;

    /* ---- embed: Xall[t][n][b] = Wemb[idx[b][t]][n] ---- */
    for (int id = gtid; id < TT*N_NEURONS; id += RBLK*RTHR) {
        int t = id >> 12;
        int n = id & (N_NEURONS-1);
        float v[8];
#pragma unroll
        for (int bb = 0; bb < 8; bb++)
            v[bb] = Wemb[(size_t)idx[bb*TT + t]*N_NEURONS + n];
        float4* o = (float4*)&g_Xall[(size_t)id*8];
        o[0] = make_float4(v[0], v[1], v[2], v[3]);
        o[1] = make_float4(v[4], v[5], v[6], v[7]);
    }

    /* ---- stage this warp's edges (CSR bins, sorted by edge id) into smem ---- */
    int nrn[NPW], grs[NPW], cnt[NPW], lb[NPW];
#pragma unroll
    for (int i = 0; i < NPW; i++) {
        nrn[i] = warp + NWARP*i;
        grs[i] = g_rowptr[nrn[i]];
        cnt[i] = g_rowptr[nrn[i]+1] - grs[i];
    }
    if (lane == 0) s_wcnt[wid] = cnt[0] + cnt[1];
    __syncthreads();
    if (tid == 0) {
        int acc = 0;
        for (int w = 0; w < NWARPS; w++) { s_wbase[w] = acc; acc += s_wcnt[w]; }
        s_wbase[NWARPS] = acc;
    }
    __syncthreads();
    lb[0] = s_wbase[wid];
    lb[1] = lb[0] + cnt[0];

    if (lane < NPW) {
        int c = cnt[lane], g0 = grs[lane], l0 = lb[lane];
        int lbuf[MAXB];
        for (int j = 0; j < c; j++) lbuf[j] = g_perm[g0 + j];
        for (int i = 1; i < c; i++) {                 /* deterministic order */
            int key = lbuf[i], j = i-1;
            while (j >= 0 && lbuf[j] > key) { lbuf[j+1] = lbuf[j]; j--; }
            lbuf[j+1] = key;
        }
        for (int j = 0; j < c; j++) s_soff[l0 + j] = lbuf[j];
    }
    __syncwarp();
    {
        int ctot = cnt[0] + cnt[1];
        for (int j = lane; j < ctot; j += 32) {
            int e = s_soff[lb[0] + j];
            int gp = (j < cnt[0]) ? (grs[0] + j) : (grs[1] + j - cnt[0]);
            g_perm[gp]        = e;         /* sorted perm for sigma scatter */
            s_soff[lb[0] + j] = srcA[e]*32;
            s_gs [lb[0] + j]  = GsA[e];
            s_gx [lb[0] + j]  = GxA[e];
            s_gy [lb[0] + j]  = GyA[e];
            s_sig[lb[0] + j]  = 0.0f;
        }
    }
    gbar();   /* embed + staging complete everywhere */

    /* ---- y0 = X[:,0,:] ---- */
#pragma unroll
    for (int i = 0; i < NPW; i++)
        if (e4 == 0) __stcg(&g_y[nrn[i]*8 + b], __ldcg(&g_Xall[nrn[i]*8 + b]));
    gbar();

    /* ---- time loop ---- */
    for (int t = 0; t < TT; t++) {
        const float* xin = g_Xall + (size_t)t*NB;
        for (int layer = 0; layer < 2; layer++) {
            /* pass1: A += x[src]*sigma ; sigma hebbian update (smem-resident) */
#pragma unroll
            for (int i = 0; i < NPW; i++) {
                int c = cnt[i], l0 = lb[i];
                float xn  = __ldcg(&xin[nrn[i]*8 + b]);
                float acc = 0.0f;
                for (int j = e4; j < c; j += 4) {
                    int   o   = s_soff[l0+j];
                    float sig = s_sig[l0+j];
                    float xv  = ldst(xin, o, b4);
                    float yv  = ldst(g_y, o, b4);
                    acc = fmaf(xv, sig, acc);
                    float p = yv * xn;
                    p += __shfl_xor_sync(gmask, p, 1);
                    p += __shfl_xor_sync(gmask, p, 2);
                    p += __shfl_xor_sync(gmask, p, 4);
                    if (b == 0)
                        s_sig[l0+j] = fmaf(p*0.125f, s_gs[l0+j], sig) * DECAYF;
                }
                acc += __shfl_xor_sync(0xffffffffu, acc, 8);
                acc += __shfl_xor_sync(0xffffffffu, acc, 16);
                if (e4 == 0) __stcg(&g_A[nrn[i]*8 + b], acc);
            }
            gbar();
            /* pass2: y = sum relu(A[src])*Gy */
#pragma unroll
            for (int i = 0; i < NPW; i++) {
                int c = cnt[i], l0 = lb[i];
                float acc = 0.0f;
                for (int j = e4; j < c; j += 4) {
                    int   o  = s_soff[l0+j];
                    float av = ldst(g_A, o, b4);
                    av = av > 0.0f ? av : 0.0f;
                    acc = fmaf(av, s_gy[l0+j], acc);
                }
                acc += __shfl_xor_sync(0xffffffffu, acc, 8);
                acc += __shfl_xor_sync(0xffffffffu, acc, 16);
                if (e4 == 0) __stcg(&g_y[nrn[i]*8 + b], acc);
            }
            gbar();
            /* pass3: x = relu(sum y[src]*Gx) */
            float* xout = (layer == 0) ? g_x : (g_xs + (size_t)t*NB);
#pragma unroll
            for (int i = 0; i < NPW; i++) {
                int c = cnt[i], l0 = lb[i];
                float acc = 0.0f;
                for (int j = e4; j < c; j += 4) {
                    int   o  = s_soff[l0+j];
                    float yv = ldst(g_y, o, b4);
                    acc = fmaf(yv, s_gx[l0+j], acc);
                }
                acc += __shfl_xor_sync(0xffffffffu, acc, 8);
                acc += __shfl_xor_sync(0xffffffffu, acc, 16);
                if (e4 == 0) __stcg(&xout[nrn[i]*8 + b], acc > 0.0f ? acc : 0.0f);
            }
            gbar();
            xin = g_x;
        }
    }

    /* ---- sigma_final scatter back to original edge order ---- */
    if (sig_out) {
#pragma unroll
        for (int i = 0; i < NPW; i++)
            for (int j = lane; j < cnt[i]; j += 32)
                sig_out[g_perm[grs[i] + j]] = s_sig[lb[i] + j];
    }
}

/* ------------------ transpose xs (t,n,b) -> (b*T+t, n) ------------------ */
__global__ void k_transpose() {
    int id = blockIdx.x*blockDim.x + threadIdx.x;
    if (id >= TT*N_NEURONS) return;
    int t = id >> 12;
    int n = id & (N_NEURONS-1);
    const float4* p = (const float4*)&g_xs[(size_t)id*8];
    float4 v0 = p[0], v1 = p[1];
    float v[8] = {v0.x, v0.y, v0.z, v0.w, v1.x, v1.y, v1.z, v1.w};
#pragma unroll
    for (int bb = 0; bb < 8; bb++)
        g_xsT[((size_t)(bb*TT + t))*N_NEURONS + n] = v[bb];
}

/* ------------------ GEMM: logits = xsT · W^T + bias ------------------ */
__global__ void __launch_bounds__(256) k_gemm(const float* __restrict__ W,
                                              const float* __restrict__ bias,
                                              float* __restrict__ out) {
    __shared__ float As[16][128+4];
    __shared__ float Bs[16][128+4];
    const int tid = threadIdx.x;
    const int tx = tid & 15, ty = tid >> 4;
    const int bv = blockIdx.x;
    const int br = blockIdx.y;
    const float* Ab = g_xsT + (size_t)br*128*N_NEURONS;
    const float* Bb = W     + (size_t)bv*128*N_NEURONS;
    const int lr = tid >> 2;
    const int lc = (tid & 3) << 2;
    float acc[8][8];
#pragma unroll
    for (int i = 0; i < 8; i++)
#pragma unroll
        for (int j = 0; j < 8; j++) acc[i][j] = 0.0f;

    for (int k0 = 0; k0 < N_NEURONS; k0 += 16) {
        float4 a0 = *(const float4*)(Ab + (size_t)lr*N_NEURONS       + k0 + lc);
        float4 a1 = *(const float4*)(Ab + (size_t)(lr+64)*N_NEURONS  + k0 + lc);
        float4 b0 = *(const float4*)(Bb + (size_t)lr*N_NEURONS       + k0 + lc);
        float4 b1 = *(const float4*)(Bb + (size_t)(lr+64)*N_NEURONS  + k0 + lc);
        __syncthreads();
        As[lc+0][lr]    = a0.x; As[lc+1][lr]    = a0.y; As[lc+2][lr]    = a0.z; As[lc+3][lr]    = a0.w;
        As[lc+0][lr+64] = a1.x; As[lc+1][lr+64] = a1.y; As[lc+2][lr+64] = a1.z; As[lc+3][lr+64] = a1.w;
        Bs[lc+0][lr]    = b0.x; Bs[lc+1][lr]    = b0.y; Bs[lc+2][lr]    = b0.z; Bs[lc+3][lr]    = b0.w;
        Bs[lc+0][lr+64] = b1.x; Bs[lc+1][lr+64] = b1.y; Bs[lc+2][lr+64] = b1.z; Bs[lc+3][lr+64] = b1.w;
        __syncthreads();
#pragma unroll
        for (int k = 0; k < 16; k++) {
            float ar[8], bc[8];
#pragma unroll
            for (int i = 0; i < 8; i++) ar[i] = As[k][ty*8 + i];
#pragma unroll
            for (int j = 0; j < 8; j++) bc[j] = Bs[k][tx*8 + j];
#pragma unroll
            for (int i = 0; i < 8; i++)
#pragma unroll
                for (int j = 0; j < 8; j++)
                    acc[i][j] = fmaf(ar[i], bc[j], acc[i][j]);
        }
    }
    const int r0 = br*128 + ty*8;
    const int v0 = bv*128 + tx*8;
#pragma unroll
    for (int i = 0; i < 8; i++)
#pragma unroll
        for (int j = 0; j < 8; j++)
            out[(size_t)(r0+i)*VOCAB + v0 + j] = acc[i][j] + bias[v0 + j];
}

/* ------------------ launch ------------------ */
extern "C" void kernel_launch(void* const* d_in, const int* in_sizes, int n_in,
                              void* d_out, int out_size) {
    const int*   idx  = (const int*)  d_in[0];
    const int*   src  = (const int*)  d_in[1];
    const int*   dst  = (const int*)  d_in[2];
    const float* Wemb = (const float*)d_in[3];
    const float* Gx   = (const float*)d_in[4];
    const float* Gy   = (const float*)d_in[5];
    const float* Gs   = (const float*)d_in[6];
    const float* Wout = (const float*)d_in[7];
    const float* bout = (const float*)d_in[8];
    float* out = (float*)d_out;

    long long btv = (long long)BB*TT*VOCAB;
    float* sig_out = ((long long)out_size >= btv + N_EDGES) ? (out + btv) : nullptr;

    k_hist   <<<512, 256>>>(dst);
    k_scan   <<<1, 1024>>>();
    k_scatter<<<512, 256>>>(dst);
    k_recurrent<<<RBLK, RTHR>>>(idx, Wemb, src, Gx, Gy, Gs, sig_out);
    k_transpose<<<(TT*N_NEURONS)/256, 256>>>();
    dim3 gg(VOCAB/128, (BB*TT)/128);
    k_gemm<<<gg, 256>>>(Wout, bout, out);
}

// round 4
// speedup vs baseline: 2.6471x; 1.2693x over previous
#include <cuda_runtime.h>
#include <cuda_bf16.h>
#include <cstdint>

#define N_NEURONS 4096
#define N_EDGES   131072
#define VOCAB     8192
#define BB        8
#define TT        128
#define NB        (N_NEURONS*BB)
#define DECAYF    0.99f

#define RBLK   128
#define RTHR   512
#define NWARPS 16
#define NWARP  (RBLK*NWARPS)
#define NPW    (N_NEURONS/NWARP)       /* 2 */
#define CAP    2048
#define MAXB   128

/* ------------------ static device scratch ------------------ */
__device__ float g_Xall[TT*NB];
__device__ float g_xs  [TT*NB];
__device__ float g_x[NB];
__device__ float g_y[NB];
__device__ float g_A[NB];
__device__ int   g_perm [N_EDGES];
__device__ int   g_counts[N_NEURONS];
__device__ int   g_cursor[N_NEURONS];
__device__ int   g_rowptr[N_NEURONS+1];
__device__ __nv_bfloat16 g_Ahi[BB*TT*N_NEURONS];
__device__ __nv_bfloat16 g_Alo[BB*TT*N_NEURONS];
__device__ __nv_bfloat16 g_Whi[VOCAB*N_NEURONS];
__device__ __nv_bfloat16 g_Wlo[VOCAB*N_NEURONS];

__device__ unsigned          g_cnt = 0;
__device__ volatile unsigned g_gen = 0;

__device__ __forceinline__ uint32_t smem_u32(const void* p) {
    uint32_t a;
    asm("{ .reg .u64 t; cvta.to.shared.u64 t, %1; cvt.u32.u64 %0, t; }" : "=r"(a) : "l"(p));
    return a;
}

/* ------------------ CSR preprocessing ------------------ */
__global__ void k_hist(const int* __restrict__ dst) {
    int e = blockIdx.x*blockDim.x + threadIdx.x;
    if (e < N_EDGES) atomicAdd(&g_counts[dst[e]], 1);
}
__global__ void k_scan() {
    __shared__ int sh[1024];
    int tid = threadIdx.x, base = tid*4;
    int v0 = g_counts[base+0], v1 = g_counts[base+1];
    int v2 = g_counts[base+2], v3 = g_counts[base+3];
    int s = v0+v1+v2+v3;
    sh[tid] = s; __syncthreads();
    for (int off = 1; off < 1024; off <<= 1) {
        int t = (tid >= off) ? sh[tid-off] : 0;
        __syncthreads(); sh[tid] += t; __syncthreads();
    }
    int excl = sh[tid] - s;
    g_rowptr[base+0] = excl; g_cursor[base+0] = excl; excl += v0;
    g_rowptr[base+1] = excl; g_cursor[base+1] = excl; excl += v1;
    g_rowptr[base+2] = excl; g_cursor[base+2] = excl; excl += v2;
    g_rowptr[base+3] = excl; g_cursor[base+3] = excl; excl += v3;
    if (tid == 1023) g_rowptr[N_NEURONS] = excl;
    g_counts[base+0]=0; g_counts[base+1]=0; g_counts[base+2]=0; g_counts[base+3]=0;
}
__global__ void k_scatter(const int* __restrict__ dst) {
    int e = blockIdx.x*blockDim.x + threadIdx.x;
    if (e < N_EDGES) { int p = atomicAdd(&g_cursor[dst[e]], 1); g_perm[p] = e; }
}

/* ------------------ W bf16 split ------------------ */
__global__ void k_convW(const float* __restrict__ W) {
    int i = blockIdx.x*blockDim.x + threadIdx.x;
    if (i >= VOCAB*N_NEURONS/4) return;
    float4 w = ((const float4*)W)[i];
    __nv_bfloat16 h[4], l[4];
    float v[4] = {w.x, w.y, w.z, w.w};
#pragma unroll
    for (int k = 0; k < 4; k++) {
        h[k] = __float2bfloat16_rn(v[k]);
        l[k] = __float2bfloat16_rn(v[k] - __bfloat162float(h[k]));
    }
    ((ushort4*)g_Whi)[i] = *(ushort4*)h;
    ((ushort4*)g_Wlo)[i] = *(ushort4*)l;
}

/* ------------------ persistent recurrent kernel ------------------ */
__device__ __forceinline__ void gbar() {
    __threadfence();
    __syncthreads();
    if (threadIdx.x == 0) {
        unsigned gen = g_gen;
        if (atomicAdd(&g_cnt, 1u) == (unsigned)(RBLK-1)) {
            g_cnt = 0; __threadfence(); g_gen = gen + 1;
        } else { while (g_gen == gen) { } }
    }
    __syncthreads();
}
__device__ __forceinline__ float ldst(const float* base, int o, int b4) {
    return __ldcg((const float*)((const char*)base + (size_t)(o + b4)));
}

__global__ void __launch_bounds__(RTHR) k_recurrent(
        const int* __restrict__ idx, const float* __restrict__ Wemb,
        const int* __restrict__ srcA, const float* __restrict__ GxA,
        const float* __restrict__ GyA, const float* __restrict__ GsA,
        float* __restrict__ sig_out)
{
    __shared__ int   s_soff[CAP];
    __shared__ float s_gs[CAP], s_gx[CAP], s_gy[CAP], s_sig[CAP];
    __shared__ int   s_wcnt[NWARPS], s_wbase[NWARPS+1];

    const int tid  = threadIdx.x;
    const int wid  = tid >> 5;
    const int lane = tid & 31;
    const int warp = blockIdx.x*NWARPS + wid;
    const int e4   = lane >> 3;
    const int b    = lane & 7;
    const int b4   = b*4;
    const unsigned gmask = 0xFFu << (e4*8);
    const int gtid = blockIdx.x*RTHR + tid;

    /* embed */
    for (int id = gtid; id < TT*N_NEURONS; id += RBLK*RTHR) {
        int t = id >> 12, n = id & (N_NEURONS-1);
        float v[8];
#pragma unroll
        for (int bb = 0; bb < 8; bb++)
            v[bb] = Wemb[(size_t)idx[bb*TT + t]*N_NEURONS + n];
        float4* o = (float4*)&g_Xall[(size_t)id*8];
        o[0] = make_float4(v[0], v[1], v[2], v[3]);
        o[1] = make_float4(v[4], v[5], v[6], v[7]);
    }

    /* stage edges (padded to 16 per neuron) */
    int nrn[NPW], grs[NPW], cnt[NPW], pc[NPW], lb[NPW];
#pragma unroll
    for (int i = 0; i < NPW; i++) {
        nrn[i] = warp + NWARP*i;
        grs[i] = g_rowptr[nrn[i]];
        cnt[i] = g_rowptr[nrn[i]+1] - grs[i];
        pc[i]  = (cnt[i] + 15) & ~15;
    }
    if (lane == 0) s_wcnt[wid] = pc[0] + pc[1];
    __syncthreads();
    if (tid == 0) {
        int acc = 0;
        for (int w = 0; w < NWARPS; w++) { s_wbase[w] = acc; acc += s_wcnt[w]; }
        s_wbase[NWARPS] = acc;
    }
    __syncthreads();
    lb[0] = s_wbase[wid];
    lb[1] = lb[0] + pc[0];

    if (lane < NPW) {
        int c = cnt[lane], g0 = grs[lane], l0 = lb[lane];
        int lbuf[MAXB];
        for (int j = 0; j < c; j++) lbuf[j] = g_perm[g0 + j];
        for (int i = 1; i < c; i++) {
            int key = lbuf[i], j = i-1;
            while (j >= 0 && lbuf[j] > key) { lbuf[j+1] = lbuf[j]; j--; }
            lbuf[j+1] = key;
        }
        for (int j = 0; j < c; j++) s_soff[l0 + j] = lbuf[j];
    }
    __syncwarp();
    {
        int ptot = pc[0] + pc[1];
        for (int j = lane; j < ptot; j += 32) {
            int pos = lb[0] + j;
            bool in0 = (j < pc[0]);
            int jj   = in0 ? j : (j - pc[0]);
            int cc   = in0 ? cnt[0] : cnt[1];
            int gp   = (in0 ? grs[0] : grs[1]) + jj;
            if (jj < cc) {
                int e = s_soff[pos];
                g_perm[gp]   = e;
                s_soff[pos]  = srcA[e]*32;
                s_gs [pos]   = GsA[e];
                s_gx [pos]   = GxA[e];
                s_gy [pos]   = GyA[e];
            } else {
                s_soff[pos] = 0; s_gs[pos] = 0.f; s_gx[pos] = 0.f; s_gy[pos] = 0.f;
            }
            s_sig[pos] = 0.0f;
        }
    }
    gbar();

    /* y0 */
#pragma unroll
    for (int i = 0; i < NPW; i++)
        if (e4 == 0) __stcg(&g_y[nrn[i]*8 + b], __ldcg(&g_Xall[nrn[i]*8 + b]));
    gbar();

    for (int t = 0; t < TT; t++) {
        const float* xin = g_Xall + (size_t)t*NB;
        for (int layer = 0; layer < 2; layer++) {
            /* pass1 */
#pragma unroll
            for (int i = 0; i < NPW; i++) {
                int c = pc[i], l0 = lb[i];
                float xn  = __ldcg(&xin[nrn[i]*8 + b]);
                float acc = 0.0f;
                for (int j = e4; j < c; j += 16) {
                    int o0 = s_soff[l0+j],    o1 = s_soff[l0+j+4];
                    int o2 = s_soff[l0+j+8],  o3 = s_soff[l0+j+12];
                    float sg0 = s_sig[l0+j],   sg1 = s_sig[l0+j+4];
                    float sg2 = s_sig[l0+j+8], sg3 = s_sig[l0+j+12];
                    float xv0 = ldst(xin,o0,b4), xv1 = ldst(xin,o1,b4);
                    float xv2 = ldst(xin,o2,b4), xv3 = ldst(xin,o3,b4);
                    float yv0 = ldst(g_y,o0,b4), yv1 = ldst(g_y,o1,b4);
                    float yv2 = ldst(g_y,o2,b4), yv3 = ldst(g_y,o3,b4);
                    acc = fmaf(xv0, sg0, acc); acc = fmaf(xv1, sg1, acc);
                    acc = fmaf(xv2, sg2, acc); acc = fmaf(xv3, sg3, acc);
                    float p0 = yv0*xn, p1 = yv1*xn, p2 = yv2*xn, p3 = yv3*xn;
                    p0 += __shfl_xor_sync(gmask, p0, 1); p1 += __shfl_xor_sync(gmask, p1, 1);
                    p2 += __shfl_xor_sync(gmask, p2, 1); p3 += __shfl_xor_sync(gmask, p3, 1);
                    p0 += __shfl_xor_sync(gmask, p0, 2); p1 += __shfl_xor_sync(gmask, p1, 2);
                    p2 += __shfl_xor_sync(gmask, p2, 2); p3 += __shfl_xor_sync(gmask, p3, 2);
                    p0 += __shfl_xor_sync(gmask, p0, 4); p1 += __shfl_xor_sync(gmask, p1, 4);
                    p2 += __shfl_xor_sync(gmask, p2, 4); p3 += __shfl_xor_sync(gmask, p3, 4);
                    if (b == 0) {
                        s_sig[l0+j]    = fmaf(p0*0.125f, s_gs[l0+j],    sg0) * DECAYF;
                        s_sig[l0+j+4]  = fmaf(p1*0.125f, s_gs[l0+j+4],  sg1) * DECAYF;
                        s_sig[l0+j+8]  = fmaf(p2*0.125f, s_gs[l0+j+8],  sg2) * DECAYF;
                        s_sig[l0+j+12] = fmaf(p3*0.125f, s_gs[l0+j+12], sg3) * DECAYF;
                    }
                }
                acc += __shfl_xor_sync(0xffffffffu, acc, 8);
                acc += __shfl_xor_sync(0xffffffffu, acc, 16);
                if (e4 == 0) __stcg(&g_A[nrn[i]*8 + b], acc);
            }
            gbar();
            /* pass2 */
#pragma unroll
            for (int i = 0; i < NPW; i++) {
                int c = pc[i], l0 = lb[i];
                float acc = 0.0f;
                for (int j = e4; j < c; j += 16) {
                    int o0 = s_soff[l0+j],   o1 = s_soff[l0+j+4];
                    int o2 = s_soff[l0+j+8], o3 = s_soff[l0+j+12];
                    float a0 = ldst(g_A,o0,b4), a1 = ldst(g_A,o1,b4);
                    float a2 = ldst(g_A,o2,b4), a3 = ldst(g_A,o3,b4);
                    a0 = a0 > 0.f ? a0 : 0.f; a1 = a1 > 0.f ? a1 : 0.f;
                    a2 = a2 > 0.f ? a2 : 0.f; a3 = a3 > 0.f ? a3 : 0.f;
                    acc = fmaf(a0, s_gy[l0+j],    acc);
                    acc = fmaf(a1, s_gy[l0+j+4],  acc);
                    acc = fmaf(a2, s_gy[l0+j+8],  acc);
                    acc = fmaf(a3, s_gy[l0+j+12], acc);
                }
                acc += __shfl_xor_sync(0xffffffffu, acc, 8);
                acc += __shfl_xor_sync(0xffffffffu, acc, 16);
                if (e4 == 0) __stcg(&g_y[nrn[i]*8 + b], acc);
            }
            gbar();
            /* pass3 */
            float* xout = (layer == 0) ? g_x : (g_xs + (size_t)t*NB);
#pragma unroll
            for (int i = 0; i < NPW; i++) {
                int c = pc[i], l0 = lb[i];
                float acc = 0.0f;
                for (int j = e4; j < c; j += 16) {
                    int o0 = s_soff[l0+j],   o1 = s_soff[l0+j+4];
                    int o2 = s_soff[l0+j+8], o3 = s_soff[l0+j+12];
                    float y0 = ldst(g_y,o0,b4), y1 = ldst(g_y,o1,b4);
                    float y2 = ldst(g_y,o2,b4), y3 = ldst(g_y,o3,b4);
                    acc = fmaf(y0, s_gx[l0+j],    acc);
                    acc = fmaf(y1, s_gx[l0+j+4],  acc);
                    acc = fmaf(y2, s_gx[l0+j+8],  acc);
                    acc = fmaf(y3, s_gx[l0+j+12], acc);
                }
                acc += __shfl_xor_sync(0xffffffffu, acc, 8);
                acc += __shfl_xor_sync(0xffffffffu, acc, 16);
                if (e4 == 0) __stcg(&xout[nrn[i]*8 + b], acc > 0.0f ? acc : 0.0f);
            }
            gbar();
            xin = g_x;
        }
    }

    if (sig_out) {
#pragma unroll
        for (int i = 0; i < NPW; i++)
            for (int j = lane; j < cnt[i]; j += 32)
                sig_out[g_perm[grs[i] + j]] = s_sig[lb[i] + j];
    }
}

/* ------------------ transpose + bf16 split of activations ------------------ */
__global__ void k_transpose() {
    int id = blockIdx.x*blockDim.x + threadIdx.x;
    if (id >= TT*N_NEURONS) return;
    int t = id >> 12, n = id & (N_NEURONS-1);
    const float4* p = (const float4*)&g_xs[(size_t)id*8];
    float4 v0 = p[0], v1 = p[1];
    float v[8] = {v0.x, v0.y, v0.z, v0.w, v1.x, v1.y, v1.z, v1.w};
#pragma unroll
    for (int bb = 0; bb < 8; bb++) {
        size_t o = (size_t)(bb*TT + t)*N_NEURONS + n;
        __nv_bfloat16 h = __float2bfloat16_rn(v[bb]);
        g_Ahi[o] = h;
        g_Alo[o] = __float2bfloat16_rn(v[bb] - __bfloat162float(h));
    }
}

/* ------------------ mma.sync bf16 GEMM (split hi/lo, 3 segments) ----------- */
#define APITCH 40                       /* bf16 elems per smem row (32 + 8 pad) */
#define STGB   (128*APITCH*2)           /* 10240 B per operand per stage */
#define NSTG   3
#define SMEM_GEMM (2*NSTG*STGB)         /* 61440 B */
#define NSTAGES_TOT 384                 /* 3 segs * 4096 / 32 */

#define LDM4(r, a) asm volatile( \
    "ldmatrix.sync.aligned.m8n8.x4.shared.b16 {%0,%1,%2,%3}, [%4];" \
    : "=r"((r)[0]), "=r"((r)[1]), "=r"((r)[2]), "=r"((r)[3]) : "r"(a))

#define MMA16816(d, a, b0r, b1r) asm volatile( \
    "mma.sync.aligned.m16n8k16.row.col.f32.bf16.bf16.f32 " \
    "{%0,%1,%2,%3},{%4,%5,%6,%7},{%8,%9},{%0,%1,%2,%3};" \
    : "+f"((d)[0]), "+f"((d)[1]), "+f"((d)[2]), "+f"((d)[3]) \
    : "r"((a)[0]), "r"((a)[1]), "r"((a)[2]), "r"((a)[3]), "r"(b0r), "r"(b1r))

__global__ void __launch_bounds__(256) k_gemm_mma(const float* __restrict__ bias,
                                                  float* __restrict__ out)
{
    extern __shared__ char smem[];
    const uint32_t sA = smem_u32(smem);
    const uint32_t sB = sA + NSTG*STGB;
    const int tid  = threadIdx.x;
    const int wid  = tid >> 5;
    const int lane = tid & 31;
    const int wm = wid & 1, wn = wid >> 1;      /* warp grid 2(M) x 4(N) */
    const int m0 = blockIdx.x * 128;
    const int n0 = blockIdx.y * 128;

    float acc[4][4][4];
#pragma unroll
    for (int i = 0; i < 4; i++)
#pragma unroll
        for (int j = 0; j < 4; j++)
#pragma unroll
            for (int k = 0; k < 4; k++) acc[i][j][k] = 0.0f;

    auto load_stage = [&](int gs, int slot) {
        int seg = gs >> 7;                      /* 0: hi·hi, 1: lo·hi, 2: hi·lo */
        int k0  = (gs & 127) << 5;
        const __nv_bfloat16* Ap = (seg == 1) ? g_Alo : g_Ahi;
        const __nv_bfloat16* Bp = (seg == 2) ? g_Wlo : g_Whi;
#pragma unroll
        for (int i = tid; i < 512; i += 256) {
            int row = i >> 2, ch = i & 3;
            uint32_t da = sA + slot*STGB + (row*APITCH + ch*8)*2;
            const __nv_bfloat16* ga = Ap + (size_t)(m0 + row)*N_NEURONS + k0 + ch*8;
            asm volatile("cp.async.cg.shared.global [%0], [%1], 16;" :: "r"(da), "l"(ga) : "memory");
        }
#pragma unroll
        for (int i = tid; i < 512; i += 256) {
            int row = i >> 2, ch = i & 3;
            uint32_t db = sB + slot*STGB + (row*APITCH + ch*8)*2;
            const __nv_bfloat16* gb = Bp + (size_t)(n0 + row)*N_NEURONS + k0 + ch*8;
            asm volatile("cp.async.cg.shared.global [%0], [%1], 16;" :: "r"(db), "l"(gb) : "memory");
        }
        asm volatile("cp.async.commit_group;" ::: "memory");
    };

    load_stage(0, 0);
    load_stage(1, 1);

    for (int it = 0; it < NSTAGES_TOT; it++) {
        if (it + 2 < NSTAGES_TOT)
            asm volatile("cp.async.wait_group 1;" ::: "memory");
        else
            asm volatile("cp.async.wait_group 0;" ::: "memory");
        __syncthreads();
        if (it + 2 < NSTAGES_TOT)
            load_stage(it + 2, (it + 2) % NSTG);

        int slot = it % NSTG;
        uint32_t aB = sA + slot*STGB;
        uint32_t bB = sB + slot*STGB;
#pragma unroll
        for (int kk = 0; kk < 2; kk++) {
            uint32_t af[4][4], bf[2][4];
#pragma unroll
            for (int mi = 0; mi < 4; mi++) {
                uint32_t addr = aB + (uint32_t)(((wm*64 + mi*16 + (lane & 15))*APITCH
                                 + kk*16 + (lane >> 4)*8) * 2);
                LDM4(af[mi], addr);
            }
#pragma unroll
            for (int nh = 0; nh < 2; nh++) {
                int mat = lane >> 3;
                uint32_t addr = bB + (uint32_t)(((wn*32 + nh*16 + (lane & 7) + (mat >> 1)*8)*APITCH
                                 + kk*16 + (mat & 1)*8) * 2);
                LDM4(bf[nh], addr);
            }
#pragma unroll
            for (int mi = 0; mi < 4; mi++)
#pragma unroll
                for (int ni = 0; ni < 4; ni++)
                    MMA16816(acc[mi][ni], af[mi], bf[ni >> 1][(ni & 1)*2], bf[ni >> 1][(ni & 1)*2 + 1]);
        }
    }

    /* epilogue */
    const int mb = m0 + wm*64;
    const int nb = n0 + wn*32;
#pragma unroll
    for (int ni = 0; ni < 4; ni++) {
        int c0 = nb + ni*8 + (lane & 3)*2;
        float bv0 = bias[c0], bv1 = bias[c0 + 1];
#pragma unroll
        for (int mi = 0; mi < 4; mi++) {
            int r0 = mb + mi*16 + (lane >> 2);
            float2 v0 = make_float2(acc[mi][ni][0] + bv0, acc[mi][ni][1] + bv1);
            float2 v1 = make_float2(acc[mi][ni][2] + bv0, acc[mi][ni][3] + bv1);
            *(float2*)&out[(size_t)r0*VOCAB + c0]       = v0;
            *(float2*)&out[(size_t)(r0 + 8)*VOCAB + c0] = v1;
        }
    }
}

/* ------------------ launch ------------------ */
extern "C" void kernel_launch(void* const* d_in, const int* in_sizes, int n_in,
                              void* d_out, int out_size) {
    const int*   idx  = (const int*)  d_in[0];
    const int*   src  = (const int*)  d_in[1];
    const int*   dst  = (const int*)  d_in[2];
    const float* Wemb = (const float*)d_in[3];
    const float* Gx   = (const float*)d_in[4];
    const float* Gy   = (const float*)d_in[5];
    const float* Gs   = (const float*)d_in[6];
    const float* Wout = (const float*)d_in[7];
    const float* bout = (const float*)d_in[8];
    float* out = (float*)d_out;

    long long btv = (long long)BB*TT*VOCAB;
    float* sig_out = ((long long)out_size >= btv + N_EDGES) ? (out + btv) : nullptr;

    static int smem_set = 0;
    if (!smem_set) {
        cudaFuncSetAttribute(k_gemm_mma, cudaFuncAttributeMaxDynamicSharedMemorySize, SMEM_GEMM);
        smem_set = 1;
    }

    k_hist   <<<512, 256>>>(dst);
    k_scan   <<<1, 1024>>>();
    k_scatter<<<512, 256>>>(dst);
    k_convW  <<<(VOCAB*N_NEURONS/4 + 255)/256, 256>>>(Wout);
    k_recurrent<<<RBLK, RTHR>>>(idx, Wemb, src, Gx, Gy, Gs, sig_out);
    k_transpose<<<(TT*N_NEURONS)/256, 256>>>();
    dim3 gg(BB*TT/128, VOCAB/128);
    k_gemm_mma<<<gg, 256, SMEM_GEMM>>>(bout, out);
}